// round 5
// baseline (speedup 1.0000x reference)
#include <cuda_runtime.h>
#include <cuda_fp16.h>
#include <cstdint>

#define NN 50000
#define NP 50048          // 391 * 128
#define FF 128
#define EE 800000
#define NTILES 3125       // EE / 256 (tile = 256 edges)

// ---------------- scratch (device globals; no allocation) ----------------
__device__ float g_ew[3][EE];
__device__ int   g_perm[3][EE];
__device__ int   g_cnt[3][NN];
__device__ int   g_off[3][NN];
__device__ int   g_cur[3][NN];
__device__ float g_dinv[3][NN];
__device__ float g_xw[(size_t)NP * FF];    // xW0, then hW1
__device__ float g_agg[(size_t)NP * FF];   // agg0 -> h (in place) -> agg1
__device__ float g_bnsum[4][FF];           // sum0, sq0, sum1, sq1
__device__ float g_bnp[4][FF];             // mu0, rs0, mu1, rs1
__device__ uint32_t g_xh[(size_t)NN * 64]; // x in fp16x2 (12.8 MB)

// packed fp32x2 FMA (Blackwell)
#define FMA2(acc, a, b) asm("fma.rn.f32x2 %0, %1, %2, %0;" : "+l"(acc) : "l"(a), "l"(b))

__device__ __forceinline__ uint32_t pack_h2(float lo, float hi) {
    __half2 h = __floats2half2_rn(lo, hi);
    return *reinterpret_cast<uint32_t*>(&h);
}

__device__ __forceinline__ uint32_t habsdiff2(uint32_t a, uint32_t b) {
    __half2 ha = *reinterpret_cast<__half2*>(&a);
    __half2 hb = *reinterpret_cast<__half2*>(&b);
    __half2 d = __habs2(__hsub2(ha, hb));
    return *reinterpret_cast<uint32_t*>(&d);
}

// warp-level fp16 tensor-core MMA, m16n8k16
__device__ __forceinline__ void mma16(float* c, const uint32_t* a, uint32_t b0, uint32_t b1) {
    asm volatile(
        "mma.sync.aligned.m16n8k16.row.col.f32.f16.f16.f32 "
        "{%0,%1,%2,%3}, {%4,%5,%6,%7}, {%8,%9}, {%0,%1,%2,%3};"
        : "+f"(c[0]), "+f"(c[1]), "+f"(c[2]), "+f"(c[3])
        : "r"(a[0]), "r"(a[1]), "r"(a[2]), "r"(a[3]), "r"(b0), "r"(b1));
}

// ---------------- small setup kernels ----------------
__global__ void k_zero() {
    int i = blockIdx.x * blockDim.x + threadIdx.x;
    if (i < 3 * NN) (&g_cnt[0][0])[i] = 0;
    if (i < 4 * FF) (&g_bnsum[0][0])[i] = 0.f;
}

__global__ void k_xh(const float* __restrict__ x) {
    int i = blockIdx.x * blockDim.x + threadIdx.x;
    if (i >= NN * 64) return;
    float2 v = ((const float2*)x)[i];
    g_xh[i] = pack_h2(v.x, v.y);
}

__global__ void k_count(const int* __restrict__ e0, const int* __restrict__ e1,
                        const int* __restrict__ e2) {
    int i = blockIdx.x * blockDim.x + threadIdx.x;
    if (i >= 3 * EE) return;
    int s = i / EE, j = i - s * EE;
    const int* col = (s == 0 ? e0 : s == 1 ? e1 : e2) + EE;
    atomicAdd(&g_cnt[s][col[j]], 1);
}

__global__ void k_scan() {
    __shared__ int sh[1024];
    __shared__ int carry;
    int s = blockIdx.x;
    int tid = threadIdx.x;
    if (tid == 0) carry = 0;
    __syncthreads();
    for (int base = 0; base < NN; base += 1024) {
        int i = base + tid;
        int v = (i < NN) ? g_cnt[s][i] : 0;
        sh[tid] = v;
        __syncthreads();
        for (int off = 1; off < 1024; off <<= 1) {
            int t = (tid >= off) ? sh[tid - off] : 0;
            __syncthreads();
            sh[tid] += t;
            __syncthreads();
        }
        int excl = sh[tid] - v;
        if (i < NN) {
            int o = carry + excl;
            g_off[s][i] = o;
            g_cur[s][i] = o;
        }
        int tot = sh[1023];
        __syncthreads();
        if (tid == 0) carry += tot;
        __syncthreads();
    }
}

__global__ void k_fill(const int* __restrict__ e0, const int* __restrict__ e1,
                       const int* __restrict__ e2) {
    int i = blockIdx.x * blockDim.x + threadIdx.x;
    if (i >= 3 * EE) return;
    int s = i / EE, j = i - s * EE;
    const int* col = (s == 0 ? e0 : s == 1 ? e1 : e2) + EE;
    int pos = atomicAdd(&g_cur[s][col[j]], 1);
    g_perm[s][pos] = j;
}

__global__ void k_deg() {
    int i = blockIdx.x * blockDim.x + threadIdx.x;
    if (i >= 3 * NN) return;
    int s = i / NN, n = i - s * NN;
    int o = g_off[s][n], c = g_cnt[s][n];
    float d = 0.f;
    for (int k = 0; k < c; ++k) d += g_ew[s][g_perm[s][o + k]];
    g_dinv[s][n] = (c > 0) ? rsqrtf(d) : 0.f;
}

// ---------------- edge MLP via fp16 mma.sync, 512 threads ----------------
// tile = 256 edges x 128 H, K=128. warp = 2 m-blocks x 8 n-blocks (half H).
// A layout: u32 addr = m*68 + ((c + 8m) & 63)   (conflict-free reads AND writes)
// W layout: u32 addr = h*68 + c                 (conflict-free reads)
#define AS_OFF  0          // 17408 u32
#define WS_OFF  17408      // 8704 u32
#define BB_OFF  26112      // 128 f
#define W2_OFF  26240      // 128 f
#define PED_OFF 26368      // 256 f
#define EW_SMEM_BYTES (26624 * 4)   // 106496 B

__global__ void __launch_bounds__(512, 1) k_edge_mlp_mma(
    const int* __restrict__ e0, const int* __restrict__ e1, const int* __restrict__ e2,
    const float* __restrict__ Wa1, const float* __restrict__ ba1,
    const float* __restrict__ Wa2, const float* __restrict__ ba2) {
    extern __shared__ uint32_t sm[];
    uint32_t* As = sm + AS_OFF;
    uint32_t* Ws = sm + WS_OFF;
    float* Bb = (float*)(sm + BB_OFF);
    float* W2 = (float*)(sm + W2_OFF);
    float* ped = (float*)(sm + PED_OFF);

    const int tid = threadIdx.x;
    const int w = tid >> 5, l = tid & 31;
    const int g = l >> 2, t = l & 3;
    const int rg = w & 7, cg = w >> 3;       // row group (32 edges), H half
    const int rowbase = rg * 32;
    const int sm_row = w * 16 + (l >> 1);    // staging: 2 threads per edge row
    const int sb = l & 1;                    // staging half (u32 cols 32*sb..)

    for (int set = 0; set < 3; ++set) {
        const int* ei = (set == 0) ? e0 : (set == 1) ? e1 : e2;
        __syncthreads();   // previous set's Ws reads complete
        {   // load W (fp16), ba1, Wa2
            const float* W = Wa1 + set * 16384;
            int h = tid >> 2, q = tid & 3;
            const float4* src = (const float4*)(W + h * 128 + q * 32);
            uint32_t* dst = Ws + h * 68 + q * 16;
#pragma unroll
            for (int i2 = 0; i2 < 8; ++i2) {
                float4 v = src[i2];
                dst[2 * i2]     = pack_h2(v.x, v.y);
                dst[2 * i2 + 1] = pack_h2(v.z, v.w);
            }
            if (tid < 128) {
                Bb[tid] = ba1[set * 128 + tid];
                W2[tid] = Wa2[set * 128 + tid];
            }
        }
        const float b2 = ba2[set];
        __syncthreads();

        for (int tile = blockIdx.x; tile < NTILES; tile += 148) {
            const int eb = tile * 256;
            // ---- stage A = fp16(|xh[r] - xh[c]|), rotated layout
            {
                int r = ei[eb + sm_row];
                int c = ei[EE + eb + sm_row];
                const uint4* xr = (const uint4*)(g_xh + (size_t)r * 64);
                const uint4* xc = (const uint4*)(g_xh + (size_t)c * 64);
                uint32_t* arow = As + sm_row * 68;
                const int rot8m = 8 * sm_row;
#pragma unroll
                for (int j = 0; j < 8; ++j) {
                    uint4 va = xr[8 * sb + j];
                    uint4 vb = xc[8 * sb + j];
                    uint4 d;
                    d.x = habsdiff2(va.x, vb.x);
                    d.y = habsdiff2(va.y, vb.y);
                    d.z = habsdiff2(va.z, vb.z);
                    d.w = habsdiff2(va.w, vb.w);
                    int sg = (32 * sb + 4 * j + rot8m) & 63;
                    *(uint4*)(arow + sg) = d;
                }
            }
            __syncthreads();   // A ready (also: prev ped reads done)

            // ---- MMA: warp = rows [rowbase, rowbase+32) x H-half cg
            float acc[2][8][4];
#pragma unroll
            for (int mb = 0; mb < 2; ++mb)
#pragma unroll
                for (int nb = 0; nb < 8; ++nb)
#pragma unroll
                    for (int q = 0; q < 4; ++q) acc[mb][nb][q] = 0.f;

#pragma unroll
            for (int kb = 0; kb < 8; ++kb) {
                const int kc = kb * 8 + t;
                uint32_t af[2][4];
#pragma unroll
                for (int mb = 0; mb < 2; ++mb) {
                    int m0 = rowbase + mb * 16 + g;
                    int base = m0 * 68;
                    int s0 = (kc + 8 * m0) & 63;
                    int s2 = (kc + 4 + 8 * m0) & 63;
                    af[mb][0] = As[base + s0];
                    af[mb][1] = As[base + 544 + s0];   // row m0+8, same sigma
                    af[mb][2] = As[base + s2];
                    af[mb][3] = As[base + 544 + s2];
                }
#pragma unroll
                for (int nb = 0; nb < 8; ++nb) {
                    int hrow = (cg * 8 + nb) * 8 + g;
                    uint32_t b0 = Ws[hrow * 68 + kc];
                    uint32_t b1 = Ws[hrow * 68 + kc + 4];
                    mma16(acc[0][nb], af[0], b0, b1);
                    mma16(acc[1][nb], af[1], b0, b1);
                }
            }

            // ---- epilogue: relu(acc+ba1).Wa2 over this warp's H-half
            float s[4] = {0.f, 0.f, 0.f, 0.f};
#pragma unroll
            for (int nb = 0; nb < 8; ++nb) {
                int h0 = (cg * 8 + nb) * 8 + 2 * t;
                float bb0 = Bb[h0], bb1 = Bb[h0 + 1];
                float w20 = W2[h0], w21 = W2[h0 + 1];
                s[0] += fmaxf(acc[0][nb][0] + bb0, 0.f) * w20 + fmaxf(acc[0][nb][1] + bb1, 0.f) * w21;
                s[1] += fmaxf(acc[0][nb][2] + bb0, 0.f) * w20 + fmaxf(acc[0][nb][3] + bb1, 0.f) * w21;
                s[2] += fmaxf(acc[1][nb][0] + bb0, 0.f) * w20 + fmaxf(acc[1][nb][1] + bb1, 0.f) * w21;
                s[3] += fmaxf(acc[1][nb][2] + bb0, 0.f) * w20 + fmaxf(acc[1][nb][3] + bb1, 0.f) * w21;
            }
#pragma unroll
            for (int i = 0; i < 4; ++i) {
                s[i] += __shfl_xor_sync(0xffffffffu, s[i], 1);
                s[i] += __shfl_xor_sync(0xffffffffu, s[i], 2);
            }
            int r0 = rowbase + g;
            if (cg == 1 && t == 0) {
                ped[r0]      = s[0];
                ped[r0 + 8]  = s[1];
                ped[r0 + 16] = s[2];
                ped[r0 + 24] = s[3];
            }
            __syncthreads();   // ped ready; all MMA reads of A done
            if (cg == 0 && t == 0) {
#pragma unroll
                for (int i = 0; i < 4; ++i) {
                    int rr = r0 + i * 8;
                    float z = s[i] + ped[rr] + b2;
                    g_ew[set][eb + rr] = 1.f / (1.f + expf(-z));
                }
            }
        }
    }
}

// ---------------- node GEMM: C[n][h] = sum_f A[n][f] * W[h][f], C = g_xw
__global__ void __launch_bounds__(256) k_gemm(
    const float* __restrict__ Aext, int nrows, const float* __restrict__ W, int useExt) {
    extern __shared__ float smf[];
    float* Ws = smf;
    float* As2 = smf + 128 * 132;
    const float* A = useExt ? Aext : (const float*)g_agg;
    const int tid = threadIdx.x;
#pragma unroll
    for (int it = 0; it < 16; ++it) {
        int idx = tid + 256 * it;
        int h = idx >> 5, f4 = idx & 31;
        float4 w = *(const float4*)(W + h * 128 + f4 * 4);
        Ws[(f4 * 4 + 0) * 132 + h] = w.x;
        Ws[(f4 * 4 + 1) * 132 + h] = w.y;
        Ws[(f4 * 4 + 2) * 132 + h] = w.z;
        Ws[(f4 * 4 + 3) * 132 + h] = w.w;
    }
    const int n0 = blockIdx.x * 128;
    const int eL = tid >> 1;
    const int jL = (tid & 1) * 4;
    const int nr = n0 + eL;
    const bool ok = nr < nrows;
    const float* ap = A + (size_t)nr * FF;
    const int tx = tid & 15, ty = tid >> 4;
    {
        float4 a = ok ? *(const float4*)(ap + jL) : make_float4(0, 0, 0, 0);
        As2[(jL + 0) * 132 + eL] = a.x;
        As2[(jL + 1) * 132 + eL] = a.y;
        As2[(jL + 2) * 132 + eL] = a.z;
        As2[(jL + 3) * 132 + eL] = a.w;
    }
    __syncthreads();

    unsigned long long acc[8][4];
#pragma unroll
    for (int r = 0; r < 8; ++r)
#pragma unroll
        for (int q = 0; q < 4; ++q) acc[r][q] = 0ull;

    for (int kt = 0; kt < 16; ++kt) {
        int buf = kt & 1;
        if (kt < 15) {
            int k0 = (kt + 1) * 8;
            float4 a = ok ? *(const float4*)(ap + k0 + jL) : make_float4(0, 0, 0, 0);
            float* D = As2 + (buf ^ 1) * 8 * 132;
            D[(jL + 0) * 132 + eL] = a.x;
            D[(jL + 1) * 132 + eL] = a.y;
            D[(jL + 2) * 132 + eL] = a.z;
            D[(jL + 3) * 132 + eL] = a.w;
        }
        const float* Ab = As2 + buf * 8 * 132;
#pragma unroll
        for (int kk = 0; kk < 8; ++kk) {
            const float* wrow = Ws + (kt * 8 + kk) * 132 + tx * 8;
            ulonglong2 b0 = *(const ulonglong2*)(wrow);
            ulonglong2 b1 = *(const ulonglong2*)(wrow + 4);
            float4 a0 = *(const float4*)(Ab + kk * 132 + ty * 8);
            float4 a1 = *(const float4*)(Ab + kk * 132 + ty * 8 + 4);
            float av[8] = {a0.x, a0.y, a0.z, a0.w, a1.x, a1.y, a1.z, a1.w};
#pragma unroll
            for (int r = 0; r < 8; ++r) {
                unsigned long long ad;
                unsigned au = __float_as_uint(av[r]);
                asm("mov.b64 %0, {%1,%1};" : "=l"(ad) : "r"(au));
                FMA2(acc[r][0], ad, b0.x);
                FMA2(acc[r][1], ad, b0.y);
                FMA2(acc[r][2], ad, b1.x);
                FMA2(acc[r][3], ad, b1.y);
            }
        }
        __syncthreads();
    }
#pragma unroll
    for (int r = 0; r < 8; ++r) {
        int n = n0 + ty * 8 + r;
        float4 o0, o1;
        o0.x = __uint_as_float((unsigned)acc[r][0]);
        o0.y = __uint_as_float((unsigned)(acc[r][0] >> 32));
        o0.z = __uint_as_float((unsigned)acc[r][1]);
        o0.w = __uint_as_float((unsigned)(acc[r][1] >> 32));
        o1.x = __uint_as_float((unsigned)acc[r][2]);
        o1.y = __uint_as_float((unsigned)(acc[r][2] >> 32));
        o1.z = __uint_as_float((unsigned)acc[r][3]);
        o1.w = __uint_as_float((unsigned)(acc[r][3] >> 32));
        *(float4*)(g_xw + (size_t)n * FF + tx * 8) = o0;
        *(float4*)(g_xw + (size_t)n * FF + tx * 8 + 4) = o1;
    }
}

// ---------------- aggregation: warp-per-node CSR gather over all 3 sets
__global__ void k_agg(const int* __restrict__ e0, const int* __restrict__ e1,
                      const int* __restrict__ e2) {
    int w = (blockIdx.x * blockDim.x + threadIdx.x) >> 5;
    if (w >= NN) return;
    int lane = threadIdx.x & 31;
    const float* src = (const float*)g_xw;
    float4 acc = make_float4(0, 0, 0, 0);
#pragma unroll
    for (int s = 0; s < 3; ++s) {
        int c = g_cnt[s][w];
        if (c == 0) continue;
        int o = g_off[s][w];
        float dc = g_dinv[s][w];
        const int* rows = (s == 0) ? e0 : (s == 1) ? e1 : e2;
        float4 pa = make_float4(0, 0, 0, 0);
        for (int k = 0; k < c; ++k) {
            int e = g_perm[s][o + k];
            int r = rows[e];
            float wt = g_ew[s][e] * g_dinv[s][r];
            float4 v = *(const float4*)(src + (size_t)r * FF + lane * 4);
            pa.x = fmaf(wt, v.x, pa.x);
            pa.y = fmaf(wt, v.y, pa.y);
            pa.z = fmaf(wt, v.z, pa.z);
            pa.w = fmaf(wt, v.w, pa.w);
        }
        acc.x = fmaf(dc, pa.x, acc.x);
        acc.y = fmaf(dc, pa.y, acc.y);
        acc.z = fmaf(dc, pa.z, acc.z);
        acc.w = fmaf(dc, pa.w, acc.w);
    }
    *(float4*)(g_agg + (size_t)w * FF + lane * 4) = acc;
}

// ---------------- bias + relu + BN stats (in place on g_agg)
__global__ void k_stats(const float* __restrict__ bias, int layer) {
    int c = threadIdx.x;
    float s = 0.f, q = 0.f;
    float b3 = 3.f * bias[c];
    for (int n = blockIdx.x; n < NN; n += gridDim.x) {
        float v = g_agg[(size_t)n * FF + c] + b3;
        v = fmaxf(v, 0.f);
        g_agg[(size_t)n * FF + c] = v;
        s += v;
        q += v * v;
    }
    atomicAdd(&g_bnsum[2 * layer][c], s);
    atomicAdd(&g_bnsum[2 * layer + 1][c], q);
}

__global__ void k_bnfin(int layer) {
    int c = threadIdx.x;
    float mu = g_bnsum[2 * layer][c] / (float)NN;
    float var = g_bnsum[2 * layer + 1][c] / (float)NN - mu * mu;
    g_bnp[2 * layer][c] = mu;
    g_bnp[2 * layer + 1][c] = rsqrtf(var + 1e-5f);
}

__global__ void k_bnapply(const float* __restrict__ gamma, const float* __restrict__ beta) {
    int i = blockIdx.x * blockDim.x + threadIdx.x;
    if (i >= NN * 32) return;
    int cb = (i & 31) * 4;
    float4 v = ((float4*)g_agg)[i];
    v.x = fmaxf((v.x - g_bnp[0][cb + 0]) * g_bnp[1][cb + 0] * gamma[cb + 0] + beta[cb + 0], 0.f);
    v.y = fmaxf((v.y - g_bnp[0][cb + 1]) * g_bnp[1][cb + 1] * gamma[cb + 1] + beta[cb + 1], 0.f);
    v.z = fmaxf((v.z - g_bnp[0][cb + 2]) * g_bnp[1][cb + 2] * gamma[cb + 2] + beta[cb + 2], 0.f);
    v.w = fmaxf((v.w - g_bnp[0][cb + 3]) * g_bnp[1][cb + 3] * gamma[cb + 3] + beta[cb + 3], 0.f);
    ((float4*)g_agg)[i] = v;
}

__global__ void k_final(const float* __restrict__ x, const float* __restrict__ gamma,
                        const float* __restrict__ beta, float* __restrict__ out) {
    int i = blockIdx.x * blockDim.x + threadIdx.x;
    if (i >= NN * 32) return;
    int cb = (i & 31) * 4;
    float4 v = ((const float4*)g_agg)[i];
    float4 xv = ((const float4*)x)[i];
    v.x = (v.x - g_bnp[2][cb + 0]) * g_bnp[3][cb + 0] * gamma[cb + 0] + beta[cb + 0] + xv.x;
    v.y = (v.y - g_bnp[2][cb + 1]) * g_bnp[3][cb + 1] * gamma[cb + 1] + beta[cb + 1] + xv.y;
    v.z = (v.z - g_bnp[2][cb + 2]) * g_bnp[3][cb + 2] * gamma[cb + 2] + beta[cb + 2] + xv.z;
    v.w = (v.w - g_bnp[2][cb + 3]) * g_bnp[3][cb + 3] * gamma[cb + 3] + beta[cb + 3] + xv.w;
    ((float4*)out)[i] = v;
}

// ---------------- launch ----------------
extern "C" void kernel_launch(void* const* d_in, const int* in_sizes, int n_in,
                              void* d_out, int out_size) {
    const float* x   = (const float*)d_in[0];
    const int*   e0  = (const int*)d_in[1];
    const int*   e1  = (const int*)d_in[2];
    const int*   e2  = (const int*)d_in[3];
    const float* Wa1 = (const float*)d_in[4];
    const float* ba1 = (const float*)d_in[5];
    const float* Wa2 = (const float*)d_in[6];
    const float* ba2 = (const float*)d_in[7];
    const float* W0  = (const float*)d_in[8];
    const float* b0  = (const float*)d_in[9];
    const float* W1  = (const float*)d_in[10];
    const float* b1  = (const float*)d_in[11];
    const float* g0  = (const float*)d_in[12];
    const float* be0 = (const float*)d_in[13];
    const float* g1  = (const float*)d_in[14];
    const float* be1 = (const float*)d_in[15];
    float* out = (float*)d_out;

    const int SMEM = (128 * 132 + 2 * 8 * 132) * 4;  // 76032 B for k_gemm
    cudaFuncSetAttribute(k_gemm, cudaFuncAttributeMaxDynamicSharedMemorySize, SMEM);
    cudaFuncSetAttribute(k_edge_mlp_mma, cudaFuncAttributeMaxDynamicSharedMemorySize,
                         EW_SMEM_BYTES);

    // edge-MLP kept as the 4th launch (ncu capture slot)
    k_zero<<<(3 * NN + 255) / 256, 256>>>();
    k_xh<<<(NN * 64 + 255) / 256, 256>>>(x);
    k_count<<<(3 * EE + 255) / 256, 256>>>(e0, e1, e2);
    k_edge_mlp_mma<<<148, 512, EW_SMEM_BYTES>>>(e0, e1, e2, Wa1, ba1, Wa2, ba2);
    k_scan<<<3, 1024>>>();
    k_fill<<<(3 * EE + 255) / 256, 256>>>(e0, e1, e2);
    k_deg<<<(3 * NN + 255) / 256, 256>>>();

    // layer 0
    k_gemm<<<NP / 128, 256, SMEM>>>(x, NN, W0, 1);
    k_agg<<<(NN * 32 + 255) / 256, 256>>>(e0, e1, e2);
    k_stats<<<512, 128>>>(b0, 0);
    k_bnfin<<<1, 128>>>(0);
    k_bnapply<<<(NN * 32 + 255) / 256, 256>>>(g0, be0);

    // layer 1
    k_gemm<<<NP / 128, 256, SMEM>>>(nullptr, NP, W1, 0);
    k_agg<<<(NN * 32 + 255) / 256, 256>>>(e0, e1, e2);
    k_stats<<<512, 128>>>(b1, 1);
    k_bnfin<<<1, 128>>>(1);
    k_final<<<(NN * 32 + 255) / 256, 256>>>(x, g1, be1, out);
}

// round 6
// speedup vs baseline: 1.8758x; 1.8758x over previous
#include <cuda_runtime.h>
#include <cuda_fp16.h>
#include <cstdint>

#define NN 50000
#define NP 50048          // 391 * 128
#define FF 128
#define EE 800000
#define NTILES 3125       // EE / 256 (tile = 256 edges)

// ---------------- scratch (device globals; no allocation) ----------------
__device__ float g_ew[3][EE];
__device__ int   g_perm[3][EE];
__device__ int   g_cnt[3][NN];
__device__ int   g_off[3][NN];
__device__ int   g_cur[3][NN];
__device__ float g_dinv[3][NN];
__device__ float g_xw[(size_t)NP * FF];    // xW0, then hW1
__device__ float g_agg[(size_t)NP * FF];   // agg0 -> h (in place) -> agg1
__device__ float g_bnsum[4][FF];           // sum0, sq0, sum1, sq1
__device__ float g_bnp[4][FF];             // mu0, rs0, mu1, rs1
__device__ uint32_t g_xh[(size_t)NN * 64]; // x in fp16x2 (12.8 MB)

// packed fp32x2 FMA (Blackwell)
#define FMA2(acc, a, b) asm("fma.rn.f32x2 %0, %1, %2, %0;" : "+l"(acc) : "l"(a), "l"(b))

__device__ __forceinline__ uint32_t pack_h2(float lo, float hi) {
    __half2 h = __floats2half2_rn(lo, hi);
    return *reinterpret_cast<uint32_t*>(&h);
}

__device__ __forceinline__ uint32_t habsdiff2(uint32_t a, uint32_t b) {
    __half2 ha = *reinterpret_cast<__half2*>(&a);
    __half2 hb = *reinterpret_cast<__half2*>(&b);
    __half2 d = __habs2(__hsub2(ha, hb));
    return *reinterpret_cast<uint32_t*>(&d);
}

__device__ __forceinline__ uint32_t smem_u32p(const void* p) {
    uint32_t a;
    asm("{ .reg .u64 t; cvta.to.shared.u64 t, %1; cvt.u32.u64 %0, t; }" : "=r"(a) : "l"(p));
    return a;
}

// warp-level fp16 tensor-core MMA, m16n8k16
__device__ __forceinline__ void mma16(float* c, const uint32_t* a, uint32_t b0, uint32_t b1) {
    asm volatile(
        "mma.sync.aligned.m16n8k16.row.col.f32.f16.f16.f32 "
        "{%0,%1,%2,%3}, {%4,%5,%6,%7}, {%8,%9}, {%0,%1,%2,%3};"
        : "+f"(c[0]), "+f"(c[1]), "+f"(c[2]), "+f"(c[3])
        : "r"(a[0]), "r"(a[1]), "r"(a[2]), "r"(a[3]), "r"(b0), "r"(b1));
}

__device__ __forceinline__ void ldsm_x4(uint32_t* r, uint32_t addr) {
    asm volatile("ldmatrix.sync.aligned.m8n8.x4.shared.b16 {%0,%1,%2,%3}, [%4];"
        : "=r"(r[0]), "=r"(r[1]), "=r"(r[2]), "=r"(r[3]) : "r"(addr));
}
__device__ __forceinline__ void ldsm_x2(uint32_t* r, uint32_t addr) {
    asm volatile("ldmatrix.sync.aligned.m8n8.x2.shared.b16 {%0,%1}, [%2];"
        : "=r"(r[0]), "=r"(r[1]) : "r"(addr));
}

// ---------------- small setup kernels ----------------
__global__ void k_zero() {
    int i = blockIdx.x * blockDim.x + threadIdx.x;
    if (i < 3 * NN) (&g_cnt[0][0])[i] = 0;
    if (i < 4 * FF) (&g_bnsum[0][0])[i] = 0.f;
}

__global__ void k_xh(const float* __restrict__ x) {
    int i = blockIdx.x * blockDim.x + threadIdx.x;
    if (i >= NN * 64) return;
    float2 v = ((const float2*)x)[i];
    g_xh[i] = pack_h2(v.x, v.y);
}

__global__ void k_count(const int* __restrict__ e0, const int* __restrict__ e1,
                        const int* __restrict__ e2) {
    int i = blockIdx.x * blockDim.x + threadIdx.x;
    if (i >= 3 * EE) return;
    int s = i / EE, j = i - s * EE;
    const int* col = (s == 0 ? e0 : s == 1 ? e1 : e2) + EE;
    atomicAdd(&g_cnt[s][col[j]], 1);
}

__global__ void k_scan() {
    __shared__ int sh[1024];
    __shared__ int carry;
    int s = blockIdx.x;
    int tid = threadIdx.x;
    if (tid == 0) carry = 0;
    __syncthreads();
    for (int base = 0; base < NN; base += 1024) {
        int i = base + tid;
        int v = (i < NN) ? g_cnt[s][i] : 0;
        sh[tid] = v;
        __syncthreads();
        for (int off = 1; off < 1024; off <<= 1) {
            int t = (tid >= off) ? sh[tid - off] : 0;
            __syncthreads();
            sh[tid] += t;
            __syncthreads();
        }
        int excl = sh[tid] - v;
        if (i < NN) {
            int o = carry + excl;
            g_off[s][i] = o;
            g_cur[s][i] = o;
        }
        int tot = sh[1023];
        __syncthreads();
        if (tid == 0) carry += tot;
        __syncthreads();
    }
}

__global__ void k_fill(const int* __restrict__ e0, const int* __restrict__ e1,
                       const int* __restrict__ e2) {
    int i = blockIdx.x * blockDim.x + threadIdx.x;
    if (i >= 3 * EE) return;
    int s = i / EE, j = i - s * EE;
    const int* col = (s == 0 ? e0 : s == 1 ? e1 : e2) + EE;
    int pos = atomicAdd(&g_cur[s][col[j]], 1);
    g_perm[s][pos] = j;
}

__global__ void k_deg() {
    int i = blockIdx.x * blockDim.x + threadIdx.x;
    if (i >= 3 * NN) return;
    int s = i / NN, n = i - s * NN;
    int o = g_off[s][n], c = g_cnt[s][n];
    float d = 0.f;
    for (int k = 0; k < c; ++k) d += g_ew[s][g_perm[s][o + k]];
    g_dinv[s][n] = (c > 0) ? rsqrtf(d) : 0.f;
}

// ---------------- edge MLP via fp16 mma.sync, 512 threads ----------------
// tile = 256 edges x 128 H, K=128. warp = 2 m-blocks x 8 n-blocks (half H).
// A layout: u32 addr = m*68 + ((c4 + 8m) & 63)   (rotated, conflict-free)
// W layout: u32 addr = h*68 + c4
#define AS_OFF  0          // 17408 u32
#define WS_OFF  17408      // 8704 u32
#define BB_OFF  26112      // 128 f
#define W2_OFF  26240      // 128 f
#define PED_OFF 26368      // 256 f
#define EW_SMEM_BYTES (26624 * 4)   // 106496 B

__global__ void __launch_bounds__(512, 1) k_edge_mlp_mma(
    const int* __restrict__ e0, const int* __restrict__ e1, const int* __restrict__ e2,
    const float* __restrict__ Wa1, const float* __restrict__ ba1,
    const float* __restrict__ Wa2, const float* __restrict__ ba2) {
    extern __shared__ uint32_t sm[];
    uint32_t* As = sm + AS_OFF;
    uint32_t* Ws = sm + WS_OFF;
    float* Bb = (float*)(sm + BB_OFF);
    float* W2 = (float*)(sm + W2_OFF);
    float* ped = (float*)(sm + PED_OFF);
    const uint32_t smA = smem_u32p(As);
    const uint32_t smW = smem_u32p(Ws);

    const int tid = threadIdx.x;
    const int w = tid >> 5, l = tid & 31;
    const int g = l >> 2, t = l & 3;
    const int rg = w & 7, cg = w >> 3;       // row group (32 edges), H half
    const int rowbase = rg * 32;

    // gather mapping: warp covers 2 edges per iter; lane = 16B chunk
    const int ge = (w << 1) + (l >> 4);      // edge slot within 32-edge stride
    const int q = l & 15;                    // uint4 chunk within row

    // ldmatrix A geometry (per lane): row within warp's 32 edges + frag column base
    const int arow0 = rowbase + ((l >> 3) & 1) * 8 + (l & 7);   // mb=0 row
    const int acb = (l >> 4) << 2;                               // 0 or 4
    const int am0base = arow0 * 68, am0rot = acb + 8 * arow0;
    const int am1base = (arow0 + 16) * 68, am1rot = acb + 8 * (arow0 + 16);
    // ldmatrix B geometry: per nb, rows h0 + (l&7), col base 8kb + ((l>>3)&1)*4
    const int bl = (l & 7), bcb = ((l >> 3) & 1) << 2;
    int hbase[8];
#pragma unroll
    for (int nb = 0; nb < 8; ++nb)
        hbase[nb] = ((cg * 8 + nb) * 8 + bl) * 68 + bcb;

    for (int set = 0; set < 3; ++set) {
        const int* ei = (set == 0) ? e0 : (set == 1) ? e1 : e2;
        __syncthreads();   // previous set's Ws reads complete
        {   // load W (fp16), ba1, Wa2
            const float* W = Wa1 + set * 16384;
            int h = tid >> 2, qq = tid & 3;
            const float4* src = (const float4*)(W + h * 128 + qq * 32);
            uint32_t* dst = Ws + h * 68 + qq * 16;
#pragma unroll
            for (int i2 = 0; i2 < 8; ++i2) {
                float4 v = src[i2];
                dst[2 * i2]     = pack_h2(v.x, v.y);
                dst[2 * i2 + 1] = pack_h2(v.z, v.w);
            }
            if (tid < 128) {
                Bb[tid] = ba1[set * 128 + tid];
                W2[tid] = Wa2[set * 128 + tid];
            }
        }
        const float b2 = ba2[set];
        __syncthreads();

        for (int tile = blockIdx.x; tile < NTILES; tile += 148) {
            const int eb = tile * 256;
            // ---- stage A = fp16(|xh[r] - xh[c]|): line-coalesced gather
#pragma unroll
            for (int j = 0; j < 8; ++j) {
                int me = j * 32 + ge;
                int r = ei[eb + me];
                int c = ei[EE + eb + me];
                uint4 va = ((const uint4*)(g_xh + (size_t)r * 64))[q];
                uint4 vb = ((const uint4*)(g_xh + (size_t)c * 64))[q];
                uint4 d;
                d.x = habsdiff2(va.x, vb.x);
                d.y = habsdiff2(va.y, vb.y);
                d.z = habsdiff2(va.z, vb.z);
                d.w = habsdiff2(va.w, vb.w);
                int idx = me * 68 + ((4 * q + 8 * me) & 63);
                *(uint4*)(As + idx) = d;
            }
            __syncthreads();   // A ready (also: prev ped reads done)

            // ---- MMA: warp = rows [rowbase, rowbase+32) x H-half cg
            float acc[2][8][4];
#pragma unroll
            for (int mb = 0; mb < 2; ++mb)
#pragma unroll
                for (int nb = 0; nb < 8; ++nb)
#pragma unroll
                    for (int qq = 0; qq < 4; ++qq) acc[mb][nb][qq] = 0.f;

#pragma unroll
            for (int kb = 0; kb < 8; ++kb) {
                uint32_t af0[4], af1[4], bf[2];
                ldsm_x4(af0, smA + 4u * (am0base + ((8 * kb + am0rot) & 63)));
                ldsm_x4(af1, smA + 4u * (am1base + ((8 * kb + am1rot) & 63)));
#pragma unroll
                for (int nb = 0; nb < 8; ++nb) {
                    ldsm_x2(bf, smW + 4u * (hbase[nb] + 8 * kb));
                    mma16(acc[0][nb], af0, bf[0], bf[1]);
                    mma16(acc[1][nb], af1, bf[0], bf[1]);
                }
            }

            // ---- epilogue: relu(acc+ba1).Wa2 over this warp's H-half
            float s[4] = {0.f, 0.f, 0.f, 0.f};
#pragma unroll
            for (int nb = 0; nb < 8; ++nb) {
                int h0 = (cg * 8 + nb) * 8 + 2 * t;
                float bb0 = Bb[h0], bb1 = Bb[h0 + 1];
                float w20 = W2[h0], w21 = W2[h0 + 1];
                s[0] += fmaxf(acc[0][nb][0] + bb0, 0.f) * w20 + fmaxf(acc[0][nb][1] + bb1, 0.f) * w21;
                s[1] += fmaxf(acc[0][nb][2] + bb0, 0.f) * w20 + fmaxf(acc[0][nb][3] + bb1, 0.f) * w21;
                s[2] += fmaxf(acc[1][nb][0] + bb0, 0.f) * w20 + fmaxf(acc[1][nb][1] + bb1, 0.f) * w21;
                s[3] += fmaxf(acc[1][nb][2] + bb0, 0.f) * w20 + fmaxf(acc[1][nb][3] + bb1, 0.f) * w21;
            }
#pragma unroll
            for (int i = 0; i < 4; ++i) {
                s[i] += __shfl_xor_sync(0xffffffffu, s[i], 1);
                s[i] += __shfl_xor_sync(0xffffffffu, s[i], 2);
            }
            int r0 = rowbase + g;
            if (cg == 1 && t == 0) {
                ped[r0]      = s[0];
                ped[r0 + 8]  = s[1];
                ped[r0 + 16] = s[2];
                ped[r0 + 24] = s[3];
            }
            __syncthreads();   // ped ready; all MMA reads of A done
            if (cg == 0 && t == 0) {
#pragma unroll
                for (int i = 0; i < 4; ++i) {
                    int rr = r0 + i * 8;
                    float z = s[i] + ped[rr] + b2;
                    g_ew[set][eb + rr] = 1.f / (1.f + expf(-z));
                }
            }
        }
    }
}

// ---------------- node GEMM: C[n][h] = sum_f A[n][f] * W[h][f], C = g_xw
__global__ void __launch_bounds__(256) k_gemm(
    const float* __restrict__ Aext, int nrows, const float* __restrict__ W, int useExt) {
    extern __shared__ float smf[];
    float* Ws = smf;
    float* As2 = smf + 128 * 132;
    const float* A = useExt ? Aext : (const float*)g_agg;
    const int tid = threadIdx.x;
#pragma unroll
    for (int it = 0; it < 16; ++it) {
        int idx = tid + 256 * it;
        int h = idx >> 5, f4 = idx & 31;
        float4 w = *(const float4*)(W + h * 128 + f4 * 4);
        Ws[(f4 * 4 + 0) * 132 + h] = w.x;
        Ws[(f4 * 4 + 1) * 132 + h] = w.y;
        Ws[(f4 * 4 + 2) * 132 + h] = w.z;
        Ws[(f4 * 4 + 3) * 132 + h] = w.w;
    }
    const int n0 = blockIdx.x * 128;
    const int eL = tid >> 1;
    const int jL = (tid & 1) * 4;
    const int nr = n0 + eL;
    const bool ok = nr < nrows;
    const float* ap = A + (size_t)nr * FF;
    const int tx = tid & 15, ty = tid >> 4;
    {
        float4 a = ok ? *(const float4*)(ap + jL) : make_float4(0, 0, 0, 0);
        As2[(jL + 0) * 132 + eL] = a.x;
        As2[(jL + 1) * 132 + eL] = a.y;
        As2[(jL + 2) * 132 + eL] = a.z;
        As2[(jL + 3) * 132 + eL] = a.w;
    }
    __syncthreads();

    unsigned long long acc[8][4];
#pragma unroll
    for (int r = 0; r < 8; ++r)
#pragma unroll
        for (int q = 0; q < 4; ++q) acc[r][q] = 0ull;

    for (int kt = 0; kt < 16; ++kt) {
        int buf = kt & 1;
        if (kt < 15) {
            int k0 = (kt + 1) * 8;
            float4 a = ok ? *(const float4*)(ap + k0 + jL) : make_float4(0, 0, 0, 0);
            float* D = As2 + (buf ^ 1) * 8 * 132;
            D[(jL + 0) * 132 + eL] = a.x;
            D[(jL + 1) * 132 + eL] = a.y;
            D[(jL + 2) * 132 + eL] = a.z;
            D[(jL + 3) * 132 + eL] = a.w;
        }
        const float* Ab = As2 + buf * 8 * 132;
#pragma unroll
        for (int kk = 0; kk < 8; ++kk) {
            const float* wrow = Ws + (kt * 8 + kk) * 132 + tx * 8;
            ulonglong2 b0 = *(const ulonglong2*)(wrow);
            ulonglong2 b1 = *(const ulonglong2*)(wrow + 4);
            float4 a0 = *(const float4*)(Ab + kk * 132 + ty * 8);
            float4 a1 = *(const float4*)(Ab + kk * 132 + ty * 8 + 4);
            float av[8] = {a0.x, a0.y, a0.z, a0.w, a1.x, a1.y, a1.z, a1.w};
#pragma unroll
            for (int r = 0; r < 8; ++r) {
                unsigned long long ad;
                unsigned au = __float_as_uint(av[r]);
                asm("mov.b64 %0, {%1,%1};" : "=l"(ad) : "r"(au));
                FMA2(acc[r][0], ad, b0.x);
                FMA2(acc[r][1], ad, b0.y);
                FMA2(acc[r][2], ad, b1.x);
                FMA2(acc[r][3], ad, b1.y);
            }
        }
        __syncthreads();
    }
#pragma unroll
    for (int r = 0; r < 8; ++r) {
        int n = n0 + ty * 8 + r;
        float4 o0, o1;
        o0.x = __uint_as_float((unsigned)acc[r][0]);
        o0.y = __uint_as_float((unsigned)(acc[r][0] >> 32));
        o0.z = __uint_as_float((unsigned)acc[r][1]);
        o0.w = __uint_as_float((unsigned)(acc[r][1] >> 32));
        o1.x = __uint_as_float((unsigned)acc[r][2]);
        o1.y = __uint_as_float((unsigned)(acc[r][2] >> 32));
        o1.z = __uint_as_float((unsigned)acc[r][3]);
        o1.w = __uint_as_float((unsigned)(acc[r][3] >> 32));
        *(float4*)(g_xw + (size_t)n * FF + tx * 8) = o0;
        *(float4*)(g_xw + (size_t)n * FF + tx * 8 + 4) = o1;
    }
}

// ---------------- aggregation: warp-per-node CSR gather over all 3 sets
__global__ void k_agg(const int* __restrict__ e0, const int* __restrict__ e1,
                      const int* __restrict__ e2) {
    int w = (blockIdx.x * blockDim.x + threadIdx.x) >> 5;
    if (w >= NN) return;
    int lane = threadIdx.x & 31;
    const float* src = (const float*)g_xw;
    float4 acc = make_float4(0, 0, 0, 0);
#pragma unroll
    for (int s = 0; s < 3; ++s) {
        int c = g_cnt[s][w];
        if (c == 0) continue;
        int o = g_off[s][w];
        float dc = g_dinv[s][w];
        const int* rows = (s == 0) ? e0 : (s == 1) ? e1 : e2;
        float4 pa = make_float4(0, 0, 0, 0);
        for (int k = 0; k < c; ++k) {
            int e = g_perm[s][o + k];
            int r = rows[e];
            float wt = g_ew[s][e] * g_dinv[s][r];
            float4 v = *(const float4*)(src + (size_t)r * FF + lane * 4);
            pa.x = fmaf(wt, v.x, pa.x);
            pa.y = fmaf(wt, v.y, pa.y);
            pa.z = fmaf(wt, v.z, pa.z);
            pa.w = fmaf(wt, v.w, pa.w);
        }
        acc.x = fmaf(dc, pa.x, acc.x);
        acc.y = fmaf(dc, pa.y, acc.y);
        acc.z = fmaf(dc, pa.z, acc.z);
        acc.w = fmaf(dc, pa.w, acc.w);
    }
    *(float4*)(g_agg + (size_t)w * FF + lane * 4) = acc;
}

// ---------------- bias + relu + BN stats (in place on g_agg)
__global__ void k_stats(const float* __restrict__ bias, int layer) {
    int c = threadIdx.x;
    float s = 0.f, q = 0.f;
    float b3 = 3.f * bias[c];
    for (int n = blockIdx.x; n < NN; n += gridDim.x) {
        float v = g_agg[(size_t)n * FF + c] + b3;
        v = fmaxf(v, 0.f);
        g_agg[(size_t)n * FF + c] = v;
        s += v;
        q += v * v;
    }
    atomicAdd(&g_bnsum[2 * layer][c], s);
    atomicAdd(&g_bnsum[2 * layer + 1][c], q);
}

__global__ void k_bnfin(int layer) {
    int c = threadIdx.x;
    float mu = g_bnsum[2 * layer][c] / (float)NN;
    float var = g_bnsum[2 * layer + 1][c] / (float)NN - mu * mu;
    g_bnp[2 * layer][c] = mu;
    g_bnp[2 * layer + 1][c] = rsqrtf(var + 1e-5f);
}

__global__ void k_bnapply(const float* __restrict__ gamma, const float* __restrict__ beta) {
    int i = blockIdx.x * blockDim.x + threadIdx.x;
    if (i >= NN * 32) return;
    int cb = (i & 31) * 4;
    float4 v = ((float4*)g_agg)[i];
    v.x = fmaxf((v.x - g_bnp[0][cb + 0]) * g_bnp[1][cb + 0] * gamma[cb + 0] + beta[cb + 0], 0.f);
    v.y = fmaxf((v.y - g_bnp[0][cb + 1]) * g_bnp[1][cb + 1] * gamma[cb + 1] + beta[cb + 1], 0.f);
    v.z = fmaxf((v.z - g_bnp[0][cb + 2]) * g_bnp[1][cb + 2] * gamma[cb + 2] + beta[cb + 2], 0.f);
    v.w = fmaxf((v.w - g_bnp[0][cb + 3]) * g_bnp[1][cb + 3] * gamma[cb + 3] + beta[cb + 3], 0.f);
    ((float4*)g_agg)[i] = v;
}

__global__ void k_final(const float* __restrict__ x, const float* __restrict__ gamma,
                        const float* __restrict__ beta, float* __restrict__ out) {
    int i = blockIdx.x * blockDim.x + threadIdx.x;
    if (i >= NN * 32) return;
    int cb = (i & 31) * 4;
    float4 v = ((const float4*)g_agg)[i];
    float4 xv = ((const float4*)x)[i];
    v.x = (v.x - g_bnp[2][cb + 0]) * g_bnp[3][cb + 0] * gamma[cb + 0] + beta[cb + 0] + xv.x;
    v.y = (v.y - g_bnp[2][cb + 1]) * g_bnp[3][cb + 1] * gamma[cb + 1] + beta[cb + 1] + xv.y;
    v.z = (v.z - g_bnp[2][cb + 2]) * g_bnp[3][cb + 2] * gamma[cb + 2] + beta[cb + 2] + xv.z;
    v.w = (v.w - g_bnp[2][cb + 3]) * g_bnp[3][cb + 3] * gamma[cb + 3] + beta[cb + 3] + xv.w;
    ((float4*)out)[i] = v;
}

// ---------------- launch ----------------
extern "C" void kernel_launch(void* const* d_in, const int* in_sizes, int n_in,
                              void* d_out, int out_size) {
    const float* x   = (const float*)d_in[0];
    const int*   e0  = (const int*)d_in[1];
    const int*   e1  = (const int*)d_in[2];
    const int*   e2  = (const int*)d_in[3];
    const float* Wa1 = (const float*)d_in[4];
    const float* ba1 = (const float*)d_in[5];
    const float* Wa2 = (const float*)d_in[6];
    const float* ba2 = (const float*)d_in[7];
    const float* W0  = (const float*)d_in[8];
    const float* b0  = (const float*)d_in[9];
    const float* W1  = (const float*)d_in[10];
    const float* b1  = (const float*)d_in[11];
    const float* g0  = (const float*)d_in[12];
    const float* be0 = (const float*)d_in[13];
    const float* g1  = (const float*)d_in[14];
    const float* be1 = (const float*)d_in[15];
    float* out = (float*)d_out;

    const int SMEM = (128 * 132 + 2 * 8 * 132) * 4;  // 76032 B for k_gemm
    cudaFuncSetAttribute(k_gemm, cudaFuncAttributeMaxDynamicSharedMemorySize, SMEM);
    cudaFuncSetAttribute(k_edge_mlp_mma, cudaFuncAttributeMaxDynamicSharedMemorySize,
                         EW_SMEM_BYTES);

    // edge-MLP kept as the 4th launch (ncu capture slot)
    k_xh<<<(NN * 64 + 255) / 256, 256>>>(x);
    k_zero<<<(3 * NN + 255) / 256, 256>>>();
    k_count<<<(3 * EE + 255) / 256, 256>>>(e0, e1, e2);
    k_edge_mlp_mma<<<148, 512, EW_SMEM_BYTES>>>(e0, e1, e2, Wa1, ba1, Wa2, ba2);
    k_scan<<<3, 1024>>>();
    k_fill<<<(3 * EE + 255) / 256, 256>>>(e0, e1, e2);
    k_deg<<<(3 * NN + 255) / 256, 256>>>();

    // layer 0
    k_gemm<<<NP / 128, 256, SMEM>>>(x, NN, W0, 1);
    k_agg<<<(NN * 32 + 255) / 256, 256>>>(e0, e1, e2);
    k_stats<<<512, 128>>>(b0, 0);
    k_bnfin<<<1, 128>>>(0);
    k_bnapply<<<(NN * 32 + 255) / 256, 256>>>(g0, be0);

    // layer 1
    k_gemm<<<NP / 128, 256, SMEM>>>(nullptr, NP, W1, 0);
    k_agg<<<(NN * 32 + 255) / 256, 256>>>(e0, e1, e2);
    k_stats<<<512, 128>>>(b1, 1);
    k_bnfin<<<1, 128>>>(1);
    k_final<<<(NN * 32 + 255) / 256, 256>>>(x, g1, be1, out);
}